// round 2
// baseline (speedup 1.0000x reference)
#include <cuda_runtime.h>
#include <float.h>

// TropicalLinear: out[n,o] = bias[o] + max_k( x[n,k] + w[o,k] )
// N=128, IN=1024, OUT=1024, fp32.
// (soft - stop_gradient(soft) == 0 exactly, so forward = max-plus GEMM + bias)
//
// Phase 1: split-K tropical GEMM, 128 CTAs (one wave), 8x8 thread tile.
// Phase 2: 4-way-parallel split reduction + bias.

#define N_ROWS  128
#define IN_DIM  1024
#define OUT_DIM 1024

#define KSPLIT  16
#define KC      (IN_DIM / KSPLIT)   // 64
#define TN      128                 // CTA n-tile (all of N)
#define TO      128                 // CTA o-tile
#define THREADS 256

// 16 * 128 * 1024 * 4B = 8 MB scratch for split-K partial maxes
__device__ float g_part[KSPLIT * N_ROWS * OUT_DIM];

__global__ __launch_bounds__(THREADS, 1)
void tropical_phase1(const float* __restrict__ x, const float* __restrict__ w)
{
    // Transposed tiles: xs[k][n], ws[k][o]  (32 KB + 32 KB static smem)
    __shared__ float xs[KC * TN];
    __shared__ float ws[KC * TO];

    const int bo = blockIdx.x;            // 0..7   (o tile)
    const int ks = blockIdx.y;            // 0..15  (k split)
    const int t  = threadIdx.x;

    const int o0 = bo * TO;
    const int k0 = ks * KC;

    // ---- fill xs[k][n]: one row (n) per thread, 8x LDG.128 covering
    //      x[n][k0..k0+31] (kh half). STS lanes vary n -> distinct banks. ----
    {
        const int n  = t & 127;
        const int kh = t >> 7;            // 0..1, 32 k each
        const float4* src = (const float4*)(x + (size_t)n * IN_DIM + k0 + kh * 32);
        #pragma unroll
        for (int j = 0; j < 8; j++) {
            float4 v = src[j];
            int k = kh * 32 + j * 4;
            xs[(k + 0) * TN + n] = v.x;
            xs[(k + 1) * TN + n] = v.y;
            xs[(k + 2) * TN + n] = v.z;
            xs[(k + 3) * TN + n] = v.w;
        }
    }
    // ---- fill ws[k][o]: same pattern over o ----
    {
        const int o  = t & 127;
        const int kh = t >> 7;
        const float4* src = (const float4*)(w + (size_t)(o0 + o) * IN_DIM + k0 + kh * 32);
        #pragma unroll
        for (int j = 0; j < 8; j++) {
            float4 v = src[j];
            int k = kh * 32 + j * 4;
            ws[(k + 0) * TO + o] = v.x;
            ws[(k + 1) * TO + o] = v.y;
            ws[(k + 2) * TO + o] = v.z;
            ws[(k + 3) * TO + o] = v.w;
        }
    }
    __syncthreads();

    // Thread tile: 8 n x 8 o.
    //   n = 8*ng + {0..7}  via xs4[k][2*ng], xs4[k][2*ng+1]   (warp broadcast)
    //   o = 4*og + {0..3}  and  64 + 4*og + {0..3}
    //       via ws4[k][og], ws4[k][og+16]                     (conflict-free)
    const int og = t & 15;
    const int ng = t >> 4;

    float acc[8][8];
    #pragma unroll
    for (int i = 0; i < 8; i++)
        #pragma unroll
        for (int j = 0; j < 8; j++)
            acc[i][j] = -FLT_MAX;

    const float4* xs4 = (const float4*)xs;   // [KC][TN/4 = 32]
    const float4* ws4 = (const float4*)ws;   // [KC][TO/4 = 32]

    #pragma unroll 2
    for (int k = 0; k < KC; k++) {
        float4 xa = xs4[k * 32 + ng * 2];
        float4 xb = xs4[k * 32 + ng * 2 + 1];
        float4 wa = ws4[k * 32 + og];
        float4 wb = ws4[k * 32 + og + 16];
        float ax[8] = {xa.x, xa.y, xa.z, xa.w, xb.x, xb.y, xb.z, xb.w};
        float aw[8] = {wa.x, wa.y, wa.z, wa.w, wb.x, wb.y, wb.z, wb.w};
        #pragma unroll
        for (int i = 0; i < 8; i++) {
            #pragma unroll
            for (int j = 0; j < 8; j++) {
                acc[i][j] = fmaxf(acc[i][j], ax[i] + aw[j]);
            }
        }
    }

    // ---- write partials: g_part[ks][n][o], coalesced float4 stores ----
    float* base = g_part + ((size_t)ks * N_ROWS + ng * 8) * OUT_DIM + o0;
    #pragma unroll
    for (int i = 0; i < 8; i++) {
        float4 p0 = make_float4(acc[i][0], acc[i][1], acc[i][2], acc[i][3]);
        float4 p1 = make_float4(acc[i][4], acc[i][5], acc[i][6], acc[i][7]);
        float4* dst = (float4*)(base + (size_t)i * OUT_DIM);
        dst[og]      = p0;   // o = o0 + 4*og
        dst[og + 16] = p1;   // o = o0 + 64 + 4*og
    }
}

__global__ __launch_bounds__(THREADS)
void tropical_phase2(const float* __restrict__ bias, float* __restrict__ out)
{
    // 4 threads per float4 output; each reduces 4 of the 16 splits,
    // then butterfly-shuffle combine within the quad.
    const int gid = blockIdx.x * THREADS + threadIdx.x;   // 0..131071
    const int idx = gid >> 2;                              // float4 out index
    const int sq  = gid & 3;                               // split quarter

    const float4* p4 = (const float4*)g_part;
    const int stride4 = N_ROWS * OUT_DIM / 4;              // 32768

    float4 m = p4[(size_t)(sq * 4) * stride4 + idx];
    #pragma unroll
    for (int j = 1; j < 4; j++) {
        float4 v = p4[(size_t)(sq * 4 + j) * stride4 + idx];
        m.x = fmaxf(m.x, v.x);
        m.y = fmaxf(m.y, v.y);
        m.z = fmaxf(m.z, v.z);
        m.w = fmaxf(m.w, v.w);
    }

    #pragma unroll
    for (int d = 1; d < 4; d <<= 1) {
        m.x = fmaxf(m.x, __shfl_xor_sync(0xffffffffu, m.x, d));
        m.y = fmaxf(m.y, __shfl_xor_sync(0xffffffffu, m.y, d));
        m.z = fmaxf(m.z, __shfl_xor_sync(0xffffffffu, m.z, d));
        m.w = fmaxf(m.w, __shfl_xor_sync(0xffffffffu, m.w, d));
    }

    if (sq == 0) {
        float4 b = __ldg(&((const float4*)bias)[idx & (OUT_DIM / 4 - 1)]);
        m.x += b.x; m.y += b.y; m.z += b.z; m.w += b.w;
        ((float4*)out)[idx] = m;
    }
}

extern "C" void kernel_launch(void* const* d_in, const int* in_sizes, int n_in,
                              void* d_out, int out_size)
{
    const float* x    = (const float*)d_in[0];   // [128, 1024]
    const float* w    = (const float*)d_in[1];   // [1024, 1024]
    const float* bias = (const float*)d_in[2];   // [1024]
    float* out = (float*)d_out;                  // [128, 1024]

    dim3 grid1(OUT_DIM / TO, KSPLIT);            // (8, 16) = 128 CTAs
    tropical_phase1<<<grid1, THREADS>>>(x, w);

    int total_threads = (N_ROWS * OUT_DIM / 4) * 4;          // 131072
    tropical_phase2<<<total_threads / THREADS, THREADS>>>(bias, out);
}

// round 3
// speedup vs baseline: 1.1098x; 1.1098x over previous
#include <cuda_runtime.h>
#include <float.h>

// TropicalLinear: out[n,o] = bias[o] + max_k( x[n,k] + w[o,k] )
// N=128, IN=1024, OUT=1024, fp32.  (soft - stop_grad(soft) == 0 exactly)
//
// Phase 1: split-K max-plus GEMM. 144 CTAs x 512 thr, f32x2 packed adds,
//          w pre-duplicated in smem as (w,w) u64 pairs -> no pack MOVs.
// Phase 2: 18-way split reduction, 2 thr per float4 output, + bias.

#define N_ROWS  128
#define IN_DIM  1024
#define OUT_DIM 1024

#define KSPLIT  18                // 4 chunks of 60 + 14 chunks of 56 = 1024
#define KCMAX   60
#define TO      128
#define THREADS 512

// smem: ws2 (dup pairs, u64) then xs (floats)
#define WS_BYTES (KCMAX * TO * 8)        // 61440
#define XS_BYTES (KCMAX * N_ROWS * 4)    // 30720
#define SMEM_BYTES (WS_BYTES + XS_BYTES) // 92160

// 18 * 128 * 1024 * 4B = 9.4 MB scratch
__device__ float g_part[KSPLIT * N_ROWS * OUT_DIM];

typedef unsigned long long ull;

__device__ __forceinline__ ull dup_f32(float v) {
    ull d;
    asm("mov.b64 %0, {%1, %1};" : "=l"(d) : "f"(v));
    return d;
}

__global__ __launch_bounds__(THREADS, 1)
void tropical_phase1(const float* __restrict__ x, const float* __restrict__ w)
{
    extern __shared__ char smem[];
    ull*   ws2 = (ull*)smem;                    // [kc][128] dup pairs
    float* xs  = (float*)(smem + WS_BYTES);     // [kc][128]

    const int bo = blockIdx.x;                  // 0..7
    const int ks = blockIdx.y;                  // 0..17
    const int t  = threadIdx.x;

    const int kc = (ks < 4) ? 60 : 56;
    const int k0 = 56 * ks + 4 * min(ks, 4);
    const int o0 = bo * TO;

    // ---- fills: thread t covers row (t&127), k-f4 group (t>>7) ----
    {
        const int r  = t & 127;
        const int kq = t >> 7;                  // 0..3
        const int nf4 = kc >> 2;                // 14 or 15

        const float4* xsrc = (const float4*)(x + (size_t)r * IN_DIM + k0);
        for (int f = kq; f < nf4; f += 4) {
            float4 v = __ldg(xsrc + f);
            int k = 4 * f;
            xs[(k + 0) * 128 + r] = v.x;
            xs[(k + 1) * 128 + r] = v.y;
            xs[(k + 2) * 128 + r] = v.z;
            xs[(k + 3) * 128 + r] = v.w;
        }
        const float4* wsrc = (const float4*)(w + (size_t)(o0 + r) * IN_DIM + k0);
        for (int f = kq; f < nf4; f += 4) {
            float4 v = __ldg(wsrc + f);
            int k = 4 * f;
            ws2[(k + 0) * 128 + r] = dup_f32(v.x);
            ws2[(k + 1) * 128 + r] = dup_f32(v.y);
            ws2[(k + 2) * 128 + r] = dup_f32(v.z);
            ws2[(k + 3) * 128 + r] = dup_f32(v.w);
        }
    }
    __syncthreads();

    // Thread tile: 8 n x 4 o.
    //   og = lane (0..31)  -> o = 4*og + {0..3}   (conflict-free v2.b64 LDS)
    //   ng = warp-constant -> n = 8*ng + {0..7}   (broadcast LDS)
    const int og = t & 31;
    const int ng = (t >> 5) & 15;

    // byte addresses in shared
    unsigned xs_addr, ws_addr;
    {
        unsigned base = (unsigned)__cvta_generic_to_shared(smem);
        ws_addr = base + (og * 4) * 8;                     // + k*1024 per row
        xs_addr = base + WS_BYTES + (ng * 8) * 4;          // + k*512  per row
    }

    float acc[8][4];
    #pragma unroll
    for (int i = 0; i < 8; i++)
        #pragma unroll
        for (int j = 0; j < 4; j++)
            acc[i][j] = -FLT_MAX;

    #pragma unroll 2
    for (int k = 0; k < kc; k++) {
        ull xp0, xp1, xp2, xp3;       // (x0,x1)(x2,x3)(x4,x5)(x6,x7)
        ull wd0, wd1, wd2, wd3;       // (w0,w0)(w1,w1)(w2,w2)(w3,w3)
        asm volatile("ld.shared.v2.b64 {%0,%1}, [%2];"
                     : "=l"(xp0), "=l"(xp1) : "r"(xs_addr + k * 512u));
        asm volatile("ld.shared.v2.b64 {%0,%1}, [%2];"
                     : "=l"(xp2), "=l"(xp3) : "r"(xs_addr + k * 512u + 16u));
        asm volatile("ld.shared.v2.b64 {%0,%1}, [%2];"
                     : "=l"(wd0), "=l"(wd1) : "r"(ws_addr + k * 1024u));
        asm volatile("ld.shared.v2.b64 {%0,%1}, [%2];"
                     : "=l"(wd2), "=l"(wd3) : "r"(ws_addr + k * 1024u + 16u));

        ull xp[4] = {xp0, xp1, xp2, xp3};
        ull wd[4] = {wd0, wd1, wd2, wd3};
        #pragma unroll
        for (int ip = 0; ip < 4; ip++) {
            #pragma unroll
            for (int j = 0; j < 4; j++) {
                ull s;
                float lo, hi;
                asm("add.rn.f32x2 %0, %1, %2;" : "=l"(s) : "l"(xp[ip]), "l"(wd[j]));
                asm("mov.b64 {%0, %1}, %2;" : "=f"(lo), "=f"(hi) : "l"(s));
                acc[2 * ip + 0][j] = fmaxf(acc[2 * ip + 0][j], lo);
                acc[2 * ip + 1][j] = fmaxf(acc[2 * ip + 1][j], hi);
            }
        }
    }

    // ---- write partials: g_part[ks][n][o], coalesced float4 stores ----
    float4* dst = (float4*)g_part
        + ((size_t)ks * N_ROWS + ng * 8) * (OUT_DIM / 4) + bo * 32 + og;
    #pragma unroll
    for (int i = 0; i < 8; i++) {
        dst[(size_t)i * (OUT_DIM / 4)] =
            make_float4(acc[i][0], acc[i][1], acc[i][2], acc[i][3]);
    }
}

__global__ __launch_bounds__(256)
void tropical_phase2(const float* __restrict__ bias, float* __restrict__ out)
{
    // 2 threads per float4 output; each reduces 9 of 18 splits (MLP=9).
    const int gid  = blockIdx.x * 256 + threadIdx.x;   // 0..65535
    const int idx  = gid >> 1;                          // float4 out index
    const int half = gid & 1;

    const float4* p4 = (const float4*)g_part;
    const int stride4 = N_ROWS * OUT_DIM / 4;           // 32768

    float4 m = p4[(size_t)(half * 9) * stride4 + idx];
    #pragma unroll
    for (int j = 1; j < 9; j++) {
        float4 v = p4[(size_t)(half * 9 + j) * stride4 + idx];
        m.x = fmaxf(m.x, v.x);
        m.y = fmaxf(m.y, v.y);
        m.z = fmaxf(m.z, v.z);
        m.w = fmaxf(m.w, v.w);
    }

    m.x = fmaxf(m.x, __shfl_xor_sync(0xffffffffu, m.x, 1));
    m.y = fmaxf(m.y, __shfl_xor_sync(0xffffffffu, m.y, 1));
    m.z = fmaxf(m.z, __shfl_xor_sync(0xffffffffu, m.z, 1));
    m.w = fmaxf(m.w, __shfl_xor_sync(0xffffffffu, m.w, 1));

    if (half == 0) {
        float4 b = __ldg(&((const float4*)bias)[idx & (OUT_DIM / 4 - 1)]);
        m.x += b.x; m.y += b.y; m.z += b.z; m.w += b.w;
        ((float4*)out)[idx] = m;
    }
}

extern "C" void kernel_launch(void* const* d_in, const int* in_sizes, int n_in,
                              void* d_out, int out_size)
{
    const float* x    = (const float*)d_in[0];   // [128, 1024]
    const float* w    = (const float*)d_in[1];   // [1024, 1024]
    const float* bias = (const float*)d_in[2];   // [1024]
    float* out = (float*)d_out;                  // [128, 1024]

    cudaFuncSetAttribute(tropical_phase1,
                         cudaFuncAttributeMaxDynamicSharedMemorySize, SMEM_BYTES);

    dim3 grid1(OUT_DIM / TO, KSPLIT);            // (8, 18) = 144 CTAs
    tropical_phase1<<<grid1, THREADS, SMEM_BYTES>>>(x, w);

    tropical_phase2<<<(N_ROWS * OUT_DIM / 4 * 2) / 256, 256>>>(bias, out);
}